// round 1
// baseline (speedup 1.0000x reference)
#include <cuda_runtime.h>
#include <math.h>

#define K_DIM 128
#define D_DIM 256
#define TILE_M 128
#define DC 32
#define NTHREADS 256

__device__ float g_c2[K_DIM];

// Precompute ||c_k||^2 for all centroids (tiny: 128x256).
__global__ void prep_kernel(const float* __restrict__ C) {
    int k = threadIdx.x;  // 128 threads
    float s = 0.f;
    const float* row = C + (size_t)k * D_DIM;
#pragma unroll 8
    for (int d = 0; d < D_DIM; ++d) {
        float v = row[d];
        s = fmaf(v, v, s);
    }
    g_c2[k] = s;
}

__global__ __launch_bounds__(NTHREADS, 2)
void assign_kernel(const float* __restrict__ seq, const float* __restrict__ u,
                   const float* __restrict__ C, float* __restrict__ assign,
                   int N) {
    __shared__ float As[DC][TILE_M + 1];
    __shared__ float Bs[DC][K_DIM + 1];
    __shared__ float c2s[K_DIM];

    const int tid = threadIdx.x;
    const int tx = tid & 15;   // k group: owns k = tx + 16*j
    const int ty = tid >> 4;   // row group: owns row = row0 + ty + 16*i
    const int row0 = blockIdx.x * TILE_M;

    if (tid < K_DIM) c2s[tid] = g_c2[tid];

    float acc[8][8];
#pragma unroll
    for (int i = 0; i < 8; i++)
#pragma unroll
        for (int j = 0; j < 8; j++) acc[i][j] = 0.f;
    float x2[8];
#pragma unroll
    for (int i = 0; i < 8; i++) x2[i] = 0.f;

    for (int d0 = 0; d0 < D_DIM; d0 += DC) {
        __syncthreads();
        // Load A tile: 128 rows x 32 d (transposed into smem), 4 float4 per thread.
#pragma unroll
        for (int it = 0; it < 4; ++it) {
            int item = tid + it * NTHREADS;  // 0..1023
            int r = item >> 3;               // 0..127
            int c = item & 7;                // 0..7 (float4 index within DC)
            int row = row0 + r;
            float4 v = make_float4(0.f, 0.f, 0.f, 0.f);
            if (row < N)
                v = *reinterpret_cast<const float4*>(&seq[(size_t)row * D_DIM + d0 + c * 4]);
            As[c * 4 + 0][r] = v.x;
            As[c * 4 + 1][r] = v.y;
            As[c * 4 + 2][r] = v.z;
            As[c * 4 + 3][r] = v.w;
        }
        // Load B tile: 128 k x 32 d (transposed into smem).
#pragma unroll
        for (int it = 0; it < 4; ++it) {
            int item = tid + it * NTHREADS;
            int r = item >> 3;
            int c = item & 7;
            float4 v = *reinterpret_cast<const float4*>(&C[(size_t)r * D_DIM + d0 + c * 4]);
            Bs[c * 4 + 0][r] = v.x;
            Bs[c * 4 + 1][r] = v.y;
            Bs[c * 4 + 2][r] = v.z;
            Bs[c * 4 + 3][r] = v.w;
        }
        __syncthreads();
#pragma unroll 4
        for (int d = 0; d < DC; ++d) {
            float a[8], b[8];
#pragma unroll
            for (int i = 0; i < 8; i++) a[i] = As[d][ty + 16 * i];
#pragma unroll
            for (int j = 0; j < 8; j++) b[j] = Bs[d][tx + 16 * j];
#pragma unroll
            for (int i = 0; i < 8; i++) {
                x2[i] = fmaf(a[i], a[i], x2[i]);
#pragma unroll
                for (int j = 0; j < 8; j++)
                    acc[i][j] = fmaf(a[i], b[j], acc[i][j]);
            }
        }
    }

    // Epilogue: logits = sqrt(max(x2 - 2*dot + c2, 0)) + gumbel(u); argmax (first index wins).
    float best[8];
    int bidx[8];
#pragma unroll
    for (int i = 0; i < 8; i++) { best[i] = -INFINITY; bidx[i] = K_DIM; }

#pragma unroll
    for (int i = 0; i < 8; i++) {
        int row = row0 + ty + 16 * i;
        if (row < N) {
#pragma unroll
            for (int j = 0; j < 8; j++) {
                int k = tx + 16 * j;
                float sq = x2[i] - 2.f * acc[i][j] + c2s[k];
                float sc = sqrtf(fmaxf(sq, 0.f));
                float uu = u[(size_t)row * K_DIM + k];
                float g = -logf(-logf(uu + 1e-10f) + 1e-10f);
                float logit = sc + g;
                // within-thread ks are ascending, strict > keeps lowest on ties
                if (logit > best[i]) { best[i] = logit; bidx[i] = k; }
            }
        }
    }

#pragma unroll
    for (int i = 0; i < 8; i++) {
        float v = best[i];
        int ix = bidx[i];
        // Reduce across the 16 lanes (same ty group) sharing this row;
        // prefer lower k on exact ties (matches jnp.argmax first-occurrence).
#pragma unroll
        for (int off = 8; off >= 1; off >>= 1) {
            float v2 = __shfl_xor_sync(0xffffffffu, v, off);
            int ix2 = __shfl_xor_sync(0xffffffffu, ix, off);
            if (v2 > v || (v2 == v && ix2 < ix)) { v = v2; ix = ix2; }
        }
        int row = row0 + ty + 16 * i;
        if (row < N) {
            float* orow = assign + (size_t)row * K_DIM;
#pragma unroll
            for (int j = 0; j < 8; j++) {
                int k = tx + 16 * j;
                orow[k] = (k == ix) ? 1.0f : 0.0f;
            }
        }
    }
}

extern "C" void kernel_launch(void* const* d_in, const int* in_sizes, int n_in,
                              void* d_out, int out_size) {
    const float* seq = (const float*)d_in[0];          // [N, 256] f32
    const float* u   = (const float*)d_in[1];          // [N, 128] f32
    const float* C   = (const float*)d_in[2];          // [128, 256] f32

    const int N = in_sizes[1] / K_DIM;
    float* out = (float*)d_out;
    float* assign = out;

    // Output tuple = (community_embed, assignmat): embed first if space for both.
    long long need_both = (long long)N * K_DIM + (long long)K_DIM * D_DIM;
    if ((long long)out_size >= need_both) {
        cudaMemcpyAsync(out, C, (size_t)K_DIM * D_DIM * sizeof(float),
                        cudaMemcpyDeviceToDevice);
        assign = out + K_DIM * D_DIM;
    }

    prep_kernel<<<1, K_DIM>>>(C);
    int grid = (N + TILE_M - 1) / TILE_M;
    assign_kernel<<<grid, NTHREADS>>>(seq, u, C, assign, N);
}

// round 4
// speedup vs baseline: 1.7044x; 1.7044x over previous
#include <cuda_runtime.h>
#include <cuda_bf16.h>
#include <cstdint>
#include <math.h>

#define K_DIM 128
#define D_DIM 256
#define TILE_M 128
#define NTHREADS 256
#define DC 64
#define SB 144             // smem row stride in bytes (72 bf16) -> conflict-free ldmatrix

// ---- dynamic smem layout (bytes) ----
#define SMEM_AH    0
#define SMEM_AL    18432
#define SMEM_BH    36864
#define SMEM_BL    55296
#define SMEM_C2    73728   // 128 f32
#define SMEM_X2    74240   // 128 f32
#define SMEM_BV    74752   // 2*128 f32 (per-half best)   | reused as fallback partials
#define SMEM_BS    75776   // 2*128 f32 (per-half second) | reused as fallback logits
#define SMEM_BI    76800   // 2*128 i32 (per-half idx)
#define SMEM_IDX   77824   // 128 i32
#define SMEM_FCNT  78336   // 1 i32
#define SMEM_FLIST 78340   // 128 i32
#define SMEM_TOTAL 78976

__device__ float g_c2[K_DIM];

// ---------------- PTX helpers (sm_80-era: valid on compute_103 base target) ----
__device__ __forceinline__ uint32_t smem_u32(const void* p) {
    uint32_t a;
    asm("{ .reg .u64 t; cvta.to.shared.u64 t, %1; cvt.u32.u64 %0, t; }"
        : "=r"(a) : "l"(p));
    return a;
}
__device__ __forceinline__ void ldsm4(uint32_t* r, uint32_t addr) {
    asm volatile("ldmatrix.sync.aligned.m8n8.x4.shared.b16 {%0,%1,%2,%3}, [%4];"
                 : "=r"(r[0]), "=r"(r[1]), "=r"(r[2]), "=r"(r[3]) : "r"(addr));
}
__device__ __forceinline__ void mma_bf16(float* d, const uint32_t* a, const uint32_t* b) {
    asm volatile("mma.sync.aligned.m16n8k16.row.col.f32.bf16.bf16.f32 "
                 "{%0,%1,%2,%3}, {%4,%5,%6,%7}, {%8,%9}, {%0,%1,%2,%3};"
                 : "+f"(d[0]), "+f"(d[1]), "+f"(d[2]), "+f"(d[3])
                 : "r"(a[0]), "r"(a[1]), "r"(a[2]), "r"(a[3]), "r"(b[0]), "r"(b[1]));
}

__device__ __forceinline__ uint32_t pack_bf2(__nv_bfloat16 a, __nv_bfloat16 b) {
    uint16_t ra = *reinterpret_cast<uint16_t*>(&a);
    uint16_t rb = *reinterpret_cast<uint16_t*>(&b);
    return (uint32_t)ra | ((uint32_t)rb << 16);
}
__device__ __forceinline__ void split_store(char* hi, char* lo, uint32_t off, float4 v) {
    __nv_bfloat16 hx = __float2bfloat16_rn(v.x), hy = __float2bfloat16_rn(v.y);
    __nv_bfloat16 hz = __float2bfloat16_rn(v.z), hw = __float2bfloat16_rn(v.w);
    __nv_bfloat16 lx = __float2bfloat16_rn(v.x - __bfloat162float(hx));
    __nv_bfloat16 ly = __float2bfloat16_rn(v.y - __bfloat162float(hy));
    __nv_bfloat16 lz = __float2bfloat16_rn(v.z - __bfloat162float(hz));
    __nv_bfloat16 lw = __float2bfloat16_rn(v.w - __bfloat162float(hw));
    *reinterpret_cast<uint2*>(hi + off) = make_uint2(pack_bf2(hx, hy), pack_bf2(hz, hw));
    *reinterpret_cast<uint2*>(lo + off) = make_uint2(pack_bf2(lx, ly), pack_bf2(lz, lw));
}

// ---------------- prep: ||c_k||^2 ----------------
__global__ void prep_kernel(const float* __restrict__ C) {
    int k = threadIdx.x;
    float s = 0.f;
    const float* row = C + (size_t)k * D_DIM;
#pragma unroll 8
    for (int d = 0; d < D_DIM; ++d) s = fmaf(row[d], row[d], s);
    g_c2[k] = s;
}

// ---------------- main ----------------
__global__ __launch_bounds__(NTHREADS, 2)
void assign_kernel(const float* __restrict__ seq, const float* __restrict__ u,
                   const float* __restrict__ C, float* __restrict__ assign,
                   int N) {
    extern __shared__ char smem[];
    const uint32_t sm = smem_u32(smem);
    const int tid = threadIdx.x;
    const int wid = tid >> 5;
    const int lane = tid & 31;
    const int row0 = blockIdx.x * TILE_M;

    float* c2s = (float*)(smem + SMEM_C2);
    float* x2s = (float*)(smem + SMEM_X2);
    float* bvs = (float*)(smem + SMEM_BV);
    float* bss = (float*)(smem + SMEM_BS);
    int*   bis = (int*)(smem + SMEM_BI);
    int*   idxs = (int*)(smem + SMEM_IDX);
    int*   fcnt = (int*)(smem + SMEM_FCNT);
    int*   flist = (int*)(smem + SMEM_FLIST);

    if (tid < K_DIM) c2s[tid] = g_c2[tid];
    if (tid == 0) *fcnt = 0;

    const int wr = wid >> 1;       // 0..3 (row group of 32)
    const int wc = wid & 1;        // 0..1 (col group of 64)

    float acc[2][8][4];
#pragma unroll
    for (int mi = 0; mi < 2; mi++)
#pragma unroll
        for (int ni = 0; ni < 8; ni++)
#pragma unroll
            for (int j = 0; j < 4; j++) acc[mi][ni][j] = 0.f;

    for (int ch = 0; ch < 4; ++ch) {
        if (ch) __syncthreads();   // prior tiles fully consumed

        // ---- load + split fp32 -> (bf16 hi, bf16 lo) tiles; accumulate x2 ----
#pragma unroll
        for (int i = 0; i < 8; ++i) {
            int f = tid + NTHREADS * i;     // 0..2047
            int row = f >> 4;
            int c4 = f & 15;
            int grow = row0 + row;
            float4 v = make_float4(0.f, 0.f, 0.f, 0.f);
            if (grow < N)
                v = *reinterpret_cast<const float4*>(seq + (size_t)grow * D_DIM + ch * DC + 4 * c4);
            float part = v.x * v.x + v.y * v.y + v.z * v.z + v.w * v.w;
#pragma unroll
            for (int o = 8; o >= 1; o >>= 1)
                part += __shfl_xor_sync(0xffffffffu, part, o);
            if ((lane & 15) == 0) {
                if (ch == 0) x2s[row] = part; else x2s[row] += part;
            }
            split_store(smem + SMEM_AH, smem + SMEM_AL, (uint32_t)row * SB + c4 * 8, v);
        }
#pragma unroll
        for (int i = 0; i < 8; ++i) {
            int f = tid + NTHREADS * i;
            int row = f >> 4;
            int c4 = f & 15;
            float4 v = *reinterpret_cast<const float4*>(C + (size_t)row * D_DIM + ch * DC + 4 * c4);
            split_store(smem + SMEM_BH, smem + SMEM_BL, (uint32_t)row * SB + c4 * 8, v);
        }
        __syncthreads();

        // ---- HMMA mainloop over 4 k16-steps ----
#pragma unroll
        for (int ks = 0; ks < 4; ++ks) {
            uint32_t ah[2][4], al[2][4];
            const uint32_t a_lane_off =
                (uint32_t)(lane & 15) * SB + (uint32_t)(lane >> 4) * 16 + (uint32_t)ks * 32;
#pragma unroll
            for (int mi = 0; mi < 2; ++mi) {
                uint32_t base = (uint32_t)(wr * 32 + mi * 16) * SB + a_lane_off;
                ldsm4(ah[mi], sm + SMEM_AH + base);
                ldsm4(al[mi], sm + SMEM_AL + base);
            }
            // B fragment: NON-trans ldmatrix from [n][k] rows.
            // lanes 0-7: n0-7/k0-7 -> b0(ngrp0); 8-15: n0-7/k8-15 -> b1(ngrp0);
            // 16-23: n8-15/k0-7 -> b0(ngrp1); 24-31: n8-15/k8-15 -> b1(ngrp1).
            const uint32_t b_lane_off =
                (uint32_t)((lane & 7) + ((lane >> 4) << 3)) * SB +
                (uint32_t)ks * 32 + (uint32_t)(((lane >> 3) & 1) << 4);
#pragma unroll
            for (int np = 0; np < 4; ++np) {
                uint32_t bbase = (uint32_t)(wc * 64 + np * 16) * SB + b_lane_off;
                uint32_t bh[4], bl[4];
                ldsm4(bh, sm + SMEM_BH + bbase);
                ldsm4(bl, sm + SMEM_BL + bbase);
#pragma unroll
                for (int mi = 0; mi < 2; ++mi) {
#pragma unroll
                    for (int t = 0; t < 2; ++t) {
                        float* d = acc[mi][np * 2 + t];
                        mma_bf16(d, ah[mi], bh + 2 * t);   // xh*ch
                        mma_bf16(d, ah[mi], bl + 2 * t);   // xh*cl
                        mma_bf16(d, al[mi], bh + 2 * t);   // xl*ch
                    }
                }
            }
        }
    }
    __syncthreads();

    // ---- epilogue: logits, per-row top-2, argmax ----
    const int g = lane >> 2;
    const int tig = lane & 3;
#pragma unroll
    for (int mi = 0; mi < 2; ++mi) {
#pragma unroll
        for (int half = 0; half < 2; ++half) {
            int row = wr * 32 + mi * 16 + g + 8 * half;
            int grow = row0 + row;
            float x2r = x2s[row];
            const float* urow = u + (size_t)(grow < N ? grow : 0) * K_DIM + wc * 64;
            float best = -INFINITY, second = -INFINITY;
            int bidx = 0;
#pragma unroll
            for (int ni = 0; ni < 8; ++ni) {
                int col = ni * 8 + tig * 2;
                float2 uu = *reinterpret_cast<const float2*>(urow + col);
#pragma unroll
                for (int j = 0; j < 2; ++j) {
                    int k = wc * 64 + col + j;
                    float dot = acc[mi][ni][2 * half + j];
                    float sq = fmaxf(x2r - 2.f * dot + c2s[k], 0.f);
                    float uv = j ? uu.y : uu.x;
                    float gb = -logf(-logf(uv + 1e-10f) + 1e-10f);
                    float lg = sqrtf(sq) + gb;
                    if (lg > best) { second = best; best = lg; bidx = k; }
                    else if (lg > second) { second = lg; }
                }
            }
            // reduce (best, second, idx) across the 4 lanes sharing this row
#pragma unroll
            for (int o = 1; o <= 2; o <<= 1) {
                float b2 = __shfl_xor_sync(0xffffffffu, best, o);
                float s2 = __shfl_xor_sync(0xffffffffu, second, o);
                int i2 = __shfl_xor_sync(0xffffffffu, bidx, o);
                float lo = fminf(best, b2);
                if (b2 > best || (b2 == best && i2 < bidx)) {
                    second = fmaxf(lo, s2); best = b2; bidx = i2;
                } else {
                    second = fmaxf(lo, second);
                }
            }
            if (tig == 0) {
                bvs[wc * 128 + row] = best;
                bss[wc * 128 + row] = second;
                bis[wc * 128 + row] = bidx;
            }
        }
    }
    __syncthreads();

    // combine halves; flag near-ties for exact fp32 recompute
    if (tid < 128) {
        float v0 = bvs[tid], v1 = bvs[128 + tid];
        float s0 = bss[tid], s1 = bss[128 + tid];
        bool h1 = (v1 > v0);
        float ball = h1 ? v1 : v0;
        float sall = fmaxf(fminf(v0, v1), h1 ? s1 : s0);
        idxs[tid] = h1 ? bis[128 + tid] : bis[tid];
        if (row0 + tid < N && ball - sall < 1e-3f) {
            int p = atomicAdd(fcnt, 1);
            flist[p] = tid;
        }
    }
    __syncthreads();

    // ---- exact fp32 fallback for flagged rows (rare) ----
    int nf = *fcnt;
    for (int f = 0; f < nf; ++f) {
        int row = flist[f];
        int grow = row0 + row;
        {
            int k = tid & 127, h = tid >> 7;
            const float* xr = seq + (size_t)grow * D_DIM + h * 128;
            const float* cr = C + (size_t)k * D_DIM + h * 128;
            float p = 0.f;
#pragma unroll 8
            for (int d = 0; d < 128; ++d) p = fmaf(xr[d], cr[d], p);
            bvs[tid] = p;   // reuse as scratch (256 floats)
        }
        __syncthreads();
        if (tid < 128) {
            float dot = bvs[tid] + bvs[tid + 128];
            float sq = fmaxf(x2s[row] - 2.f * dot + c2s[tid], 0.f);
            float uv = u[(size_t)grow * K_DIM + tid];
            bss[tid] = sqrtf(sq) - logf(-logf(uv + 1e-10f) + 1e-10f);
        }
        __syncthreads();
        if (tid == 0) {
            float bv = -INFINITY; int bi = 0;
            for (int k = 0; k < K_DIM; ++k)
                if (bss[k] > bv) { bv = bss[k]; bi = k; }
            idxs[row] = bi;
        }
        __syncthreads();
    }

    // ---- coalesced one-hot store ----
#pragma unroll
    for (int it = 0; it < 16; ++it) {
        int item = tid + NTHREADS * it;   // 0..4095
        int row = item >> 5;
        int c4 = item & 31;
        int grow = row0 + row;
        if (grow < N) {
            int hot = idxs[row];
            float4 o = make_float4(0.f, 0.f, 0.f, 0.f);
            if ((hot >> 2) == c4) reinterpret_cast<float*>(&o)[hot & 3] = 1.0f;
            *reinterpret_cast<float4*>(assign + (size_t)grow * K_DIM + 4 * c4) = o;
        }
    }
}

extern "C" void kernel_launch(void* const* d_in, const int* in_sizes, int n_in,
                              void* d_out, int out_size) {
    const float* seq = (const float*)d_in[0];  // [N,256]
    const float* u   = (const float*)d_in[1];  // [N,128]
    const float* C   = (const float*)d_in[2];  // [128,256]

    const int N = in_sizes[1] / K_DIM;
    float* out = (float*)d_out;
    float* assign = out;

    long long need_both = (long long)N * K_DIM + (long long)K_DIM * D_DIM;
    if ((long long)out_size >= need_both) {
        cudaMemcpyAsync(out, C, (size_t)K_DIM * D_DIM * sizeof(float),
                        cudaMemcpyDeviceToDevice);
        assign = out + K_DIM * D_DIM;
    }

    prep_kernel<<<1, K_DIM>>>(C);

    cudaFuncSetAttribute(assign_kernel,
                         cudaFuncAttributeMaxDynamicSharedMemorySize, SMEM_TOTAL);
    int grid = (N + TILE_M - 1) / TILE_M;
    assign_kernel<<<grid, NTHREADS, SMEM_TOTAL>>>(seq, u, C, assign, N);
}